// round 1
// baseline (speedup 1.0000x reference)
#include <cuda_runtime.h>
#include <cuda_bf16.h>
#include <cstdint>

// Problem constants
#define BB   64
#define NN   4096
#define EE   4096
#define NNZ  32768
#define CC   256

// ---------------- static device scratch (no allocs allowed) ----------------
__device__ float g_y   [(size_t)BB * NN * CC];   // 268 MB
__device__ float g_edge[(size_t)BB * EE * CC];   // 268 MB
__device__ float g_W12 [CC * CC];
__device__ float g_bvec[CC];

__device__ int   g_deg_e[EE], g_deg_n[NN];
__device__ int   g_off_e[EE + 1], g_off_n[NN + 1];
__device__ int   g_cur_e[EE], g_cur_n[NN];
__device__ int   g_adj_e[NNZ];   // grouped by dst(edge), values = src(node)
__device__ int   g_adj_n[NNZ];   // grouped by src(node), values = dst(edge)
__device__ float g_binv[EE], g_dinv[NN];

// ---------------- setup kernels ----------------
__global__ void zero_kernel() {
    int i = blockIdx.x * blockDim.x + threadIdx.x;
    if (i < EE) g_deg_e[i] = 0;
    if (i < NN) g_deg_n[i] = 0;
}

__global__ void deg_kernel(const int* __restrict__ hidx) {
    int i = blockIdx.x * blockDim.x + threadIdx.x;
    if (i >= NNZ) return;
    int s = hidx[i];
    int d = hidx[NNZ + i];
    atomicAdd(&g_deg_n[s], 1);
    atomicAdd(&g_deg_e[d], 1);
}

// blockIdx.x == 0 : edge degrees -> g_off_e / g_cur_e / g_binv
// blockIdx.x == 1 : node degrees -> g_off_n / g_cur_n / g_dinv
__global__ void scan_kernel() {
    const int which = blockIdx.x;
    const int* deg = which ? g_deg_n : g_deg_e;
    int* off       = which ? g_off_n : g_off_e;
    int* cur       = which ? g_cur_n : g_cur_e;
    float* inv     = which ? g_dinv  : g_binv;

    __shared__ int sm[1024];
    int t = threadIdx.x;
    int d0 = deg[t * 4 + 0];
    int d1 = deg[t * 4 + 1];
    int d2 = deg[t * 4 + 2];
    int d3 = deg[t * 4 + 3];
    int s = d0 + d1 + d2 + d3;
    sm[t] = s;
    __syncthreads();
    for (int o = 1; o < 1024; o <<= 1) {
        int v = (t >= o) ? sm[t - o] : 0;
        __syncthreads();
        sm[t] += v;
        __syncthreads();
    }
    int base = sm[t] - s;
    int p0 = base;
    int p1 = p0 + d0;
    int p2 = p1 + d1;
    int p3 = p2 + d2;
    off[t * 4 + 0] = p0; cur[t * 4 + 0] = p0;
    off[t * 4 + 1] = p1; cur[t * 4 + 1] = p1;
    off[t * 4 + 2] = p2; cur[t * 4 + 2] = p2;
    off[t * 4 + 3] = p3; cur[t * 4 + 3] = p3;
    inv[t * 4 + 0] = d0 > 0 ? 1.0f / (float)d0 : 0.0f;
    inv[t * 4 + 1] = d1 > 0 ? 1.0f / (float)d1 : 0.0f;
    inv[t * 4 + 2] = d2 > 0 ? 1.0f / (float)d2 : 0.0f;
    inv[t * 4 + 3] = d3 > 0 ? 1.0f / (float)d3 : 0.0f;
    if (t == 1023) off[4096] = p3 + d3;
}

__global__ void fill_kernel(const int* __restrict__ hidx) {
    int i = blockIdx.x * blockDim.x + threadIdx.x;
    if (i >= NNZ) return;
    int s = hidx[i];
    int d = hidx[NNZ + i];
    int p = atomicAdd(&g_cur_e[d], 1);
    g_adj_e[p] = s;
    int q = atomicAdd(&g_cur_n[s], 1);
    g_adj_n[q] = d;
}

// W12 = W1 @ W2 ; bvec = b1 @ W2.  grid = 257 blocks of 256 threads.
__global__ void w12_kernel(const float* __restrict__ W1,
                           const float* __restrict__ b1,
                           const float* __restrict__ W2) {
    __shared__ float row[CC];
    int j = threadIdx.x;
    int i = blockIdx.x;
    if (i < CC) {
        row[j] = W1[i * CC + j];
        __syncthreads();
        float acc = 0.0f;
#pragma unroll 8
        for (int k = 0; k < CC; k++) acc += row[k] * W2[k * CC + j];
        g_W12[i * CC + j] = acc;
    } else {
        row[j] = b1[j];
        __syncthreads();
        float acc = 0.0f;
#pragma unroll 8
        for (int k = 0; k < CC; k++) acc += row[k] * W2[k * CC + j];
        g_bvec[j] = acc;
    }
}

// ---------------- big GEMM: g_y = X[M,256] @ g_W12[256,256] ----------------
// BM=128, BN=128, BK=16, 256 threads, 8x8 per thread. grid = (M/128, 2).
#define GM_BM 128
#define GM_BN 128
#define GM_BK 16

__global__ __launch_bounds__(256) void gemm_kernel(const float* __restrict__ A) {
    __shared__ float As[GM_BK][GM_BM + 1];   // +1 pad: conflict-light transposed stores
    __shared__ float Bs[GM_BK][GM_BN];

    const int tid = threadIdx.x;
    const int m0 = blockIdx.x * GM_BM;
    const int n0 = blockIdx.y * GM_BN;
    const int tx = tid & 15;
    const int ty = tid >> 4;

    float acc[8][8];
#pragma unroll
    for (int i = 0; i < 8; i++)
#pragma unroll
        for (int j = 0; j < 8; j++) acc[i][j] = 0.0f;

    for (int k0 = 0; k0 < CC; k0 += GM_BK) {
        // load A tile 128x16 (512 float4, 2 per thread), store transposed
#pragma unroll
        for (int l = 0; l < 2; l++) {
            int lid = tid + l * 256;
            int r = lid >> 2;
            int c4 = (lid & 3) << 2;
            float4 v = *(const float4*)&A[(size_t)(m0 + r) * CC + k0 + c4];
            As[c4 + 0][r] = v.x;
            As[c4 + 1][r] = v.y;
            As[c4 + 2][r] = v.z;
            As[c4 + 3][r] = v.w;
        }
        // load B tile 16x128
#pragma unroll
        for (int l = 0; l < 2; l++) {
            int lid = tid + l * 256;
            int r = lid >> 5;
            int c4 = (lid & 31) << 2;
            *(float4*)&Bs[r][c4] = *(const float4*)&g_W12[(k0 + r) * CC + n0 + c4];
        }
        __syncthreads();
#pragma unroll
        for (int kk = 0; kk < GM_BK; kk++) {
            float ra[8], rb[8];
#pragma unroll
            for (int i = 0; i < 8; i++) ra[i] = As[kk][ty * 8 + i];
#pragma unroll
            for (int j = 0; j < 8; j++) rb[j] = Bs[kk][tx * 8 + j];
#pragma unroll
            for (int i = 0; i < 8; i++)
#pragma unroll
                for (int j = 0; j < 8; j++) acc[i][j] += ra[i] * rb[j];
        }
        __syncthreads();
    }
#pragma unroll
    for (int i = 0; i < 8; i++) {
        size_t r = (size_t)(m0 + ty * 8 + i);
#pragma unroll
        for (int j = 0; j < 8; j += 4) {
            float4 v = make_float4(acc[i][j], acc[i][j + 1], acc[i][j + 2], acc[i][j + 3]);
            *(float4*)&g_y[r * CC + n0 + tx * 8 + j] = v;
        }
    }
}

// ---------------- aggregation (one S half-step) ----------------
// One block handles segment g for 4 batches. 64 lanes x float4 cover C=256.
// in_sel/out_sel: 0=external ptr, 1=g_y, 2=g_edge
// use_edge_csr: 1 -> gather nodes into edge g (CSR by dst); 0 -> gather edges into node g
// final_mode: add u[n]*bvec + b2
__global__ __launch_bounds__(256) void agg_kernel(const float* __restrict__ ext_in,
                                                  float* __restrict__ ext_out,
                                                  int in_sel, int out_sel,
                                                  int use_edge_csr, int final_mode,
                                                  const float* __restrict__ b2) {
    const int* off   = use_edge_csr ? g_off_e : g_off_n;
    const int* adj   = use_edge_csr ? g_adj_e : g_adj_n;
    const float* inv = use_edge_csr ? g_binv  : g_dinv;
    const float* in  = (in_sel == 0) ? ext_in  : (in_sel == 1 ? g_y : g_edge);
    float* out       = (out_sel == 0) ? ext_out : (out_sel == 1 ? g_y : g_edge);

    __shared__ int sidx[256];
    const int g    = blockIdx.x;
    const int lane = threadIdx.x & 63;
    const int bsub = threadIdx.x >> 6;
    const int b    = (blockIdx.y << 2) + bsub;

    const int s = off[g];
    const int e = off[g + 1];

    const float4* inf4 = (const float4*)in + ((size_t)b << 18) + lane; // b*4096*64 f4

    float4 acc = make_float4(0.f, 0.f, 0.f, 0.f);
    for (int cs = s; cs < e; cs += 256) {
        int cnt = e - cs;
        if (cnt > 256) cnt = 256;
        __syncthreads();
        if (threadIdx.x < cnt) sidx[threadIdx.x] = adj[cs + threadIdx.x];
        __syncthreads();
        for (int i = 0; i < cnt; i++) {
            float4 v = inf4[(size_t)sidx[i] * 64];
            acc.x += v.x; acc.y += v.y; acc.z += v.z; acc.w += v.w;
        }
    }

    const float sc = inv[g];
    acc.x *= sc; acc.y *= sc; acc.z *= sc; acc.w *= sc;

    if (final_mode) {
        float u = (sc > 0.0f) ? 1.0f : 0.0f;
        float4 bv  = ((const float4*)g_bvec)[lane];
        float4 b2v = ((const float4*)b2)[lane];
        acc.x += u * bv.x + b2v.x;
        acc.y += u * bv.y + b2v.y;
        acc.z += u * bv.z + b2v.z;
        acc.w += u * bv.w + b2v.w;
    }

    ((float4*)out)[((size_t)b << 18) + (size_t)g * 64 + lane] = acc;
}

// ---------------- launch ----------------
extern "C" void kernel_launch(void* const* d_in, const int* in_sizes, int n_in,
                              void* d_out, int out_size) {
    const float* x    = (const float*)d_in[0];
    const int*   hidx = (const int*)d_in[1];   // [2, NNZ]: row0 src, row1 dst
    const float* W1   = (const float*)d_in[2];
    const float* b1   = (const float*)d_in[3];
    const float* W2   = (const float*)d_in[4];
    const float* b2   = (const float*)d_in[5];
    float* out = (float*)d_out;

    // setup: degrees, CSRs, fused weights
    zero_kernel<<<16, 256>>>();
    deg_kernel<<<NNZ / 256, 256>>>(hidx);
    scan_kernel<<<2, 1024>>>();
    fill_kernel<<<NNZ / 256, 256>>>(hidx);
    w12_kernel<<<CC + 1, 256>>>(W1, b1, W2);

    // Y0 = X @ (W1 W2)   [262144 x 256]
    gemm_kernel<<<dim3((BB * NN) / GM_BM, CC / GM_BN), 256>>>(x);

    // S application #1:  g_edge = Binv * H^T Y0 ;  g_y = Dinv * H g_edge
    agg_kernel<<<dim3(EE, BB / 4), 256>>>(nullptr, nullptr, 1, 2, 1, 0, nullptr);
    agg_kernel<<<dim3(NN, BB / 4), 256>>>(nullptr, nullptr, 2, 1, 0, 0, nullptr);

    // S application #2:  g_edge = Binv * H^T Y1 ;  out = Dinv * H g_edge + u*bvec + b2
    agg_kernel<<<dim3(EE, BB / 4), 256>>>(nullptr, nullptr, 1, 2, 1, 0, nullptr);
    agg_kernel<<<dim3(NN, BB / 4), 256>>>(nullptr, out, 2, 0, 0, 1, b2);
}

// round 3
// speedup vs baseline: 1.3346x; 1.3346x over previous
#include <cuda_runtime.h>
#include <cuda_bf16.h>
#include <cstdint>

// Problem constants
#define BB   64
#define NN   4096
#define EE   4096
#define NNZ  32768
#define CC   256

// ---------------- static device scratch (no allocs allowed) ----------------
__device__ float g_y   [(size_t)BB * NN * CC];   // 268 MB  (Z buffers / GEMM A)
__device__ float g_edge[(size_t)BB * EE * CC];   // 268 MB
__device__ float g_W12p[CC * CC];                // W1@W2, n-major, k-permuted, tf32
__device__ float g_bvec[CC];                     // b1@W2

__device__ int   g_deg_e[EE], g_deg_n[NN];
__device__ int   g_off_e[EE + 1], g_off_n[NN + 1];
__device__ int   g_cur_e[EE], g_cur_n[NN];
__device__ int   g_adj_e[NNZ];   // grouped by dst(edge), values = src(node)
__device__ int   g_adj_n[NNZ];   // grouped by src(node), values = dst(edge)
__device__ float g_binv[EE], g_dinv[NN];

// ---------------- setup kernels ----------------
__global__ void zero_kernel() {
    int i = blockIdx.x * blockDim.x + threadIdx.x;
    if (i < EE) g_deg_e[i] = 0;
    if (i < NN) g_deg_n[i] = 0;
}

__global__ void deg_kernel(const int* __restrict__ hidx) {
    int i = blockIdx.x * blockDim.x + threadIdx.x;
    if (i >= NNZ) return;
    int s = hidx[i];
    int d = hidx[NNZ + i];
    atomicAdd(&g_deg_n[s], 1);
    atomicAdd(&g_deg_e[d], 1);
}

__global__ void scan_kernel() {
    const int which = blockIdx.x;
    const int* deg = which ? g_deg_n : g_deg_e;
    int* off       = which ? g_off_n : g_off_e;
    int* cur       = which ? g_cur_n : g_cur_e;
    float* inv     = which ? g_dinv  : g_binv;

    __shared__ int sm[1024];
    int t = threadIdx.x;
    int d0 = deg[t * 4 + 0];
    int d1 = deg[t * 4 + 1];
    int d2 = deg[t * 4 + 2];
    int d3 = deg[t * 4 + 3];
    int s = d0 + d1 + d2 + d3;
    sm[t] = s;
    __syncthreads();
    for (int o = 1; o < 1024; o <<= 1) {
        int v = (t >= o) ? sm[t - o] : 0;
        __syncthreads();
        sm[t] += v;
        __syncthreads();
    }
    int base = sm[t] - s;
    int p0 = base;
    int p1 = p0 + d0;
    int p2 = p1 + d1;
    int p3 = p2 + d2;
    off[t * 4 + 0] = p0; cur[t * 4 + 0] = p0;
    off[t * 4 + 1] = p1; cur[t * 4 + 1] = p1;
    off[t * 4 + 2] = p2; cur[t * 4 + 2] = p2;
    off[t * 4 + 3] = p3; cur[t * 4 + 3] = p3;
    inv[t * 4 + 0] = d0 > 0 ? 1.0f / (float)d0 : 0.0f;
    inv[t * 4 + 1] = d1 > 0 ? 1.0f / (float)d1 : 0.0f;
    inv[t * 4 + 2] = d2 > 0 ? 1.0f / (float)d2 : 0.0f;
    inv[t * 4 + 3] = d3 > 0 ? 1.0f / (float)d3 : 0.0f;
    if (t == 1023) off[4096] = p3 + d3;
}

__global__ void fill_kernel(const int* __restrict__ hidx) {
    int i = blockIdx.x * blockDim.x + threadIdx.x;
    if (i >= NNZ) return;
    int s = hidx[i];
    int d = hidx[NNZ + i];
    int p = atomicAdd(&g_cur_e[d], 1);
    g_adj_e[p] = s;
    int q = atomicAdd(&g_cur_n[s], 1);
    g_adj_n[q] = d;
}

// W12 = W1 @ W2 (stored n-major, k-permuted, tf32) ; bvec = b1 @ W2.
__global__ void w12_kernel(const float* __restrict__ W1,
                           const float* __restrict__ b1,
                           const float* __restrict__ W2) {
    __shared__ float row[CC];
    int j = threadIdx.x;
    int i = blockIdx.x;
    if (i < CC) {
        row[j] = W1[i * CC + j];
        __syncthreads();
        float acc = 0.0f;
#pragma unroll 8
        for (int k = 0; k < CC; k++) acc += row[k] * W2[k * CC + j];
        // k index = i ; permute within 32-chunk: c -> (c%4)*8 + (c/4)%8, tf32
        int cl = i & 31;
        int s = (i & ~31) + ((cl & 3) << 3) + (cl >> 2);
        uint32_t u;
        asm("cvt.rna.tf32.f32 %0, %1;" : "=r"(u) : "f"(acc));
        g_W12p[j * CC + s] = __uint_as_float(u);
    } else {
        row[j] = b1[j];
        __syncthreads();
        float acc = 0.0f;
#pragma unroll 8
        for (int k = 0; k < CC; k++) acc += row[k] * W2[k * CC + j];
        g_bvec[j] = acc;
    }
}

// ---------------- aggregation (one S half-step) ----------------
// One block handles segment g for 4 batches. 64 lanes x float4 cover C=256.
__global__ __launch_bounds__(256) void agg_kernel(const float* __restrict__ ext_in,
                                                  int in_sel, int out_sel,
                                                  int use_edge_csr, int permute_mode,
                                                  int b_base) {
    const int* off   = use_edge_csr ? g_off_e : g_off_n;
    const int* adj   = use_edge_csr ? g_adj_e : g_adj_n;
    const float* inv = use_edge_csr ? g_binv  : g_dinv;
    const float* in  = (in_sel == 0) ? ext_in  : (in_sel == 1 ? g_y : g_edge);
    float* out       = (out_sel == 1) ? g_y : g_edge;

    __shared__ int sidx[256];
    const int g    = blockIdx.x;
    const int lane = threadIdx.x & 63;
    const int bsub = threadIdx.x >> 6;
    const int b    = b_base + (blockIdx.y << 2) + bsub;

    const int s = off[g];
    const int e = off[g + 1];

    const float4* inf4 = (const float4*)in + ((size_t)b << 18) + lane; // b*4096*64 f4

    float4 acc = make_float4(0.f, 0.f, 0.f, 0.f);
    for (int cs = s; cs < e; cs += 256) {
        int cnt = e - cs;
        if (cnt > 256) cnt = 256;
        __syncthreads();
        if (threadIdx.x < cnt) sidx[threadIdx.x] = adj[cs + threadIdx.x];
        __syncthreads();
        for (int i = 0; i < cnt; i++) {
            float4 v = inf4[(size_t)sidx[i] * 64];
            acc.x += v.x; acc.y += v.y; acc.z += v.z; acc.w += v.w;
        }
    }

    const float sc = inv[g];
    acc.x *= sc; acc.y *= sc; acc.z *= sc; acc.w *= sc;

    if (permute_mode) {
        // cols c = 4*lane + i ; within 32-chunk permute c -> (c%4)*8 + (c/4)%8
        int chunk = lane >> 3;
        int r8 = lane & 7;
        size_t base = ((size_t)b << 20) + ((size_t)g << 8) + (chunk << 5) + r8;
        uint32_t u0, u1, u2, u3;
        asm("cvt.rna.tf32.f32 %0, %1;" : "=r"(u0) : "f"(acc.x));
        asm("cvt.rna.tf32.f32 %0, %1;" : "=r"(u1) : "f"(acc.y));
        asm("cvt.rna.tf32.f32 %0, %1;" : "=r"(u2) : "f"(acc.z));
        asm("cvt.rna.tf32.f32 %0, %1;" : "=r"(u3) : "f"(acc.w));
        out[base + 0]  = __uint_as_float(u0);
        out[base + 8]  = __uint_as_float(u1);
        out[base + 16] = __uint_as_float(u2);
        out[base + 24] = __uint_as_float(u3);
    } else {
        ((float4*)out)[((size_t)b << 18) + (size_t)g * 64 + lane] = acc;
    }
}

// ---------------- tensor-core GEMM: out = g_y(perm,tf32) @ W12p + u*bvec + b2 ----
// BM=128, BN=128, k-chunk 32, 256 threads (8 warps: 4 m x 2 n), warp tile 32x64.
#define GPAD 36

__device__ __forceinline__ void mma_tf32(float4& c,
                                         uint32_t a0, uint32_t a1, uint32_t a2, uint32_t a3,
                                         uint32_t b0, uint32_t b1) {
    asm("mma.sync.aligned.m16n8k8.row.col.f32.tf32.tf32.f32 "
        "{%0,%1,%2,%3}, {%4,%5,%6,%7}, {%8,%9}, {%0,%1,%2,%3};"
        : "+f"(c.x), "+f"(c.y), "+f"(c.z), "+f"(c.w)
        : "r"(a0), "r"(a1), "r"(a2), "r"(a3), "r"(b0), "r"(b1));
}

__global__ __launch_bounds__(256, 1) void gemm_tc(float* __restrict__ C,
                                                  const float* __restrict__ b2) {
    __shared__ float As[128 * GPAD];
    __shared__ float Bs[128 * GPAD];

    const int tid  = threadIdx.x;
    const int wid  = tid >> 5;
    const int lane = tid & 31;
    const int g    = lane >> 2;
    const int t    = lane & 3;
    const int wm   = wid & 3;      // 4 warps along M (32 rows each)
    const int wn   = wid >> 2;     // 2 warps along N (64 cols each)
    const int m0   = blockIdx.x * 128;
    const int n0   = blockIdx.y * 128;

    float4 acc[2][8];
#pragma unroll
    for (int mt = 0; mt < 2; mt++)
#pragma unroll
        for (int nt = 0; nt < 8; nt++) acc[mt][nt] = make_float4(0.f, 0.f, 0.f, 0.f);

    // NOTE: device symbols referenced from device code (host cannot pass them!)
    const float4* A4 = (const float4*)g_y;
    const float4* B4 = (const float4*)g_W12p;

    // ldg assignment: f4 id = i*256 + tid ; row = id>>3, c4 = id&7
    float4 ra[4], rb[4];
#pragma unroll
    for (int i = 0; i < 4; i++) {
        int id = i * 256 + tid;
        int row = id >> 3, c4 = id & 7;
        ra[i] = A4[((size_t)(m0 + row) << 6) + c4];
        rb[i] = B4[((size_t)(n0 + row) << 6) + c4];
    }

    for (int kc = 0; kc < 8; kc++) {
#pragma unroll
        for (int i = 0; i < 4; i++) {
            int id = i * 256 + tid;
            int row = id >> 3, c4 = id & 7;
            *(float4*)&As[row * GPAD + c4 * 4] = ra[i];
            *(float4*)&Bs[row * GPAD + c4 * 4] = rb[i];
        }
        __syncthreads();
        if (kc < 7) {
#pragma unroll
            for (int i = 0; i < 4; i++) {
                int id = i * 256 + tid;
                int row = id >> 3, c4 = id & 7;
                ra[i] = A4[((size_t)(m0 + row) << 6) + (kc + 1) * 8 + c4];
                rb[i] = B4[((size_t)(n0 + row) << 6) + (kc + 1) * 8 + c4];
            }
        }
#pragma unroll
        for (int half = 0; half < 2; half++) {
            float4 alo[2], ahi[2], bb[8];
#pragma unroll
            for (int mt = 0; mt < 2; mt++) {
                int r = wm * 32 + mt * 16 + g;
                alo[mt] = *(const float4*)&As[r * GPAD + t * 8 + half * 4];
                ahi[mt] = *(const float4*)&As[(r + 8) * GPAD + t * 8 + half * 4];
            }
#pragma unroll
            for (int nt = 0; nt < 8; nt++) {
                int n = wn * 64 + nt * 8 + g;
                bb[nt] = *(const float4*)&Bs[n * GPAD + t * 8 + half * 4];
            }
#pragma unroll
            for (int mt = 0; mt < 2; mt++) {
                uint32_t a0j0 = __float_as_uint(alo[mt].x), a2j0 = __float_as_uint(alo[mt].y);
                uint32_t a0j1 = __float_as_uint(alo[mt].z), a2j1 = __float_as_uint(alo[mt].w);
                uint32_t a1j0 = __float_as_uint(ahi[mt].x), a3j0 = __float_as_uint(ahi[mt].y);
                uint32_t a1j1 = __float_as_uint(ahi[mt].z), a3j1 = __float_as_uint(ahi[mt].w);
#pragma unroll
                for (int nt = 0; nt < 8; nt++) {
                    mma_tf32(acc[mt][nt], a0j0, a1j0, a2j0, a3j0,
                             __float_as_uint(bb[nt].x), __float_as_uint(bb[nt].y));
                    mma_tf32(acc[mt][nt], a0j1, a1j1, a2j1, a3j1,
                             __float_as_uint(bb[nt].z), __float_as_uint(bb[nt].w));
                }
            }
        }
        __syncthreads();
    }

    // epilogue: c += u(row)*bvec[col] + b2[col]
#pragma unroll
    for (int mt = 0; mt < 2; mt++) {
        int r = m0 + wm * 32 + mt * 16 + g;
        float u0 = (g_dinv[r & (NN - 1)] > 0.f) ? 1.f : 0.f;
        float u1 = (g_dinv[(r + 8) & (NN - 1)] > 0.f) ? 1.f : 0.f;
#pragma unroll
        for (int nt = 0; nt < 8; nt++) {
            int col = n0 + wn * 64 + nt * 8 + 2 * t;
            float bv0 = g_bvec[col], bv1 = g_bvec[col + 1];
            float c0 = b2[col], c1 = b2[col + 1];
            float2 lo = make_float2(acc[mt][nt].x + u0 * bv0 + c0,
                                    acc[mt][nt].y + u0 * bv1 + c1);
            float2 hi = make_float2(acc[mt][nt].z + u1 * bv0 + c0,
                                    acc[mt][nt].w + u1 * bv1 + c1);
            *(float2*)&C[(size_t)r * CC + col] = lo;
            *(float2*)&C[(size_t)(r + 8) * CC + col] = hi;
        }
    }
}

// ---------------- launch ----------------
extern "C" void kernel_launch(void* const* d_in, const int* in_sizes, int n_in,
                              void* d_out, int out_size) {
    const float* x    = (const float*)d_in[0];
    const int*   hidx = (const int*)d_in[1];   // [2, NNZ]: row0 src, row1 dst
    const float* W1   = (const float*)d_in[2];
    const float* b1   = (const float*)d_in[3];
    const float* W2   = (const float*)d_in[4];
    const float* b2   = (const float*)d_in[5];
    float* out = (float*)d_out;

    // setup: degrees, CSRs, fused weights
    zero_kernel<<<16, 256>>>();
    deg_kernel<<<NNZ / 256, 256>>>(hidx);
    scan_kernel<<<2, 1024>>>();
    fill_kernel<<<NNZ / 256, 256>>>(hidx);
    w12_kernel<<<CC + 1, 256>>>(W1, b1, W2);

    // S application #1: x -> g_edge -> g_y   (batch groups of 16 keep edge slab in L2)
    for (int bb = 0; bb < BB; bb += 16) {
        agg_kernel<<<dim3(EE, 4), 256>>>(x, 0, 2, 1, 0, bb);
        agg_kernel<<<dim3(NN, 4), 256>>>(nullptr, 2, 1, 0, 0, bb);
    }
    // S application #2: g_y -> g_edge -> g_y (tf32 + k-permuted for GEMM)
    for (int bb = 0; bb < BB; bb += 16) {
        agg_kernel<<<dim3(EE, 4), 256>>>(nullptr, 1, 2, 1, 0, bb);
        agg_kernel<<<dim3(NN, 4), 256>>>(nullptr, 2, 1, 0, 1, bb);
    }

    // out = Z2 @ W12 + u*bvec + b2
    gemm_tc<<<dim3((BB * NN) / 128, CC / 128), 256>>>(out, b2);
}

// round 9
// speedup vs baseline: 1.4421x; 1.0806x over previous
#include <cuda_runtime.h>
#include <cuda_fp16.h>
#include <cstdint>

// Problem constants
#define BB   64
#define NN   4096
#define EE   4096
#define NNZ  32768
#define CC   256

// ---------------- static device scratch (no allocs allowed) ----------------
__device__ float g_y   [(size_t)BB * NN * CC];     // 268 MB (GEMM A, tf32 perm)
__device__ __half g_ahf[(size_t)BB * NN * CC];     // 134 MB (X_h, then Z1)
__device__ __half g_ehf[(size_t)BB * EE * CC];     // 134 MB (edge intermediate)
__device__ float g_W12p[CC * CC];                  // W1@W2, n-major, k-perm, tf32
__device__ float g_bvec[CC];                       // b1@W2

__device__ int   g_deg_e[EE], g_deg_n[NN];
__device__ int   g_off_e[EE + 1], g_off_n[NN + 1];
__device__ int   g_cur_e[EE], g_cur_n[NN];
__device__ int   g_adj_e[NNZ];   // grouped by dst(edge), values = src(node)
__device__ int   g_adj_n[NNZ];   // grouped by src(node), values = dst(edge)
__device__ float g_binv[EE], g_dinv[NN];

// ---------------- setup kernels ----------------
__global__ void zero_kernel() {
    int i = blockIdx.x * blockDim.x + threadIdx.x;
    if (i < EE) g_deg_e[i] = 0;
    if (i < NN) g_deg_n[i] = 0;
}

__global__ void deg_kernel(const int* __restrict__ hidx) {
    int i = blockIdx.x * blockDim.x + threadIdx.x;
    if (i >= NNZ) return;
    int s = hidx[i];
    int d = hidx[NNZ + i];
    atomicAdd(&g_deg_n[s], 1);
    atomicAdd(&g_deg_e[d], 1);
}

__global__ void scan_kernel() {
    const int which = blockIdx.x;
    const int* deg = which ? g_deg_n : g_deg_e;
    int* off       = which ? g_off_n : g_off_e;
    int* cur       = which ? g_cur_n : g_cur_e;
    float* inv     = which ? g_dinv  : g_binv;

    __shared__ int sm[1024];
    int t = threadIdx.x;
    int d0 = deg[t * 4 + 0];
    int d1 = deg[t * 4 + 1];
    int d2 = deg[t * 4 + 2];
    int d3 = deg[t * 4 + 3];
    int s = d0 + d1 + d2 + d3;
    sm[t] = s;
    __syncthreads();
    for (int o = 1; o < 1024; o <<= 1) {
        int v = (t >= o) ? sm[t - o] : 0;
        __syncthreads();
        sm[t] += v;
        __syncthreads();
    }
    int base = sm[t] - s;
    int p0 = base;
    int p1 = p0 + d0;
    int p2 = p1 + d1;
    int p3 = p2 + d2;
    off[t * 4 + 0] = p0; cur[t * 4 + 0] = p0;
    off[t * 4 + 1] = p1; cur[t * 4 + 1] = p1;
    off[t * 4 + 2] = p2; cur[t * 4 + 2] = p2;
    off[t * 4 + 3] = p3; cur[t * 4 + 3] = p3;
    inv[t * 4 + 0] = d0 > 0 ? 1.0f / (float)d0 : 0.0f;
    inv[t * 4 + 1] = d1 > 0 ? 1.0f / (float)d1 : 0.0f;
    inv[t * 4 + 2] = d2 > 0 ? 1.0f / (float)d2 : 0.0f;
    inv[t * 4 + 3] = d3 > 0 ? 1.0f / (float)d3 : 0.0f;
    if (t == 1023) off[4096] = p3 + d3;
}

__global__ void fill_kernel(const int* __restrict__ hidx) {
    int i = blockIdx.x * blockDim.x + threadIdx.x;
    if (i >= NNZ) return;
    int s = hidx[i];
    int d = hidx[NNZ + i];
    int p = atomicAdd(&g_cur_e[d], 1);
    g_adj_e[p] = s;
    int q = atomicAdd(&g_cur_n[s], 1);
    g_adj_n[q] = d;
}

// X fp32 -> g_ahf fp16 (8 elements per thread)
__global__ __launch_bounds__(256) void conv_kernel(const float* __restrict__ x) {
    size_t id = (size_t)blockIdx.x * 256 + threadIdx.x;
    const float4* x4 = (const float4*)x;
    float4 a = x4[id * 2 + 0];
    float4 b = x4[id * 2 + 1];
    __half2 p0 = __floats2half2_rn(a.x, a.y);
    __half2 p1 = __floats2half2_rn(a.z, a.w);
    __half2 p2 = __floats2half2_rn(b.x, b.y);
    __half2 p3 = __floats2half2_rn(b.z, b.w);
    uint4 o;
    o.x = *(uint32_t*)&p0; o.y = *(uint32_t*)&p1;
    o.z = *(uint32_t*)&p2; o.w = *(uint32_t*)&p3;
    ((uint4*)g_ahf)[id] = o;
}

// W12 = W1 @ W2 (stored n-major, k-permuted, tf32) ; bvec = b1 @ W2.
__global__ void w12_kernel(const float* __restrict__ W1,
                           const float* __restrict__ b1,
                           const float* __restrict__ W2) {
    __shared__ float row[CC];
    int j = threadIdx.x;
    int i = blockIdx.x;
    if (i < CC) {
        row[j] = W1[i * CC + j];
        __syncthreads();
        float acc = 0.0f;
#pragma unroll 8
        for (int k = 0; k < CC; k++) acc += row[k] * W2[k * CC + j];
        // k index = i ; permute within 32-chunk: c -> (c%4)*8 + (c/4)%8, tf32
        int cl = i & 31;
        int s = (i & ~31) + ((cl & 3) << 3) + (cl >> 2);
        uint32_t u;
        asm("cvt.rna.tf32.f32 %0, %1;" : "=r"(u) : "f"(acc));
        g_W12p[j * CC + s] = __uint_as_float(u);
    } else {
        row[j] = b1[j];
        __syncthreads();
        float acc = 0.0f;
#pragma unroll 8
        for (int k = 0; k < CC; k++) acc += row[k] * W2[k * CC + j];
        g_bvec[j] = acc;
    }
}

// ---------------- fp16 aggregation (one S half-step) ----------------
// One block: segment g x 4 batches. 64 lanes x uint2 (4 fp16 ch) cover C=256.
// Batch slab = 4096 rows * 64 uint2 = 2^18 uint2.
// in_sel: 1 = g_ahf, 2 = g_ehf
// out_sel: 1 = g_ahf (fp16), 2 = g_ehf (fp16), 3 = g_y (fp32, tf32 k-permuted)
__global__ __launch_bounds__(256) void agg_hf(int in_sel, int out_sel,
                                              int use_edge_csr, int b_base) {
    const int* off   = use_edge_csr ? g_off_e : g_off_n;
    const int* adj   = use_edge_csr ? g_adj_e : g_adj_n;
    const float* inv = use_edge_csr ? g_binv  : g_dinv;
    const __half* in = (in_sel == 1) ? g_ahf : g_ehf;

    __shared__ int sidx[256];
    const int g    = blockIdx.x;
    const int lane = threadIdx.x & 63;
    const int bsub = threadIdx.x >> 6;
    const int b    = b_base + (blockIdx.y << 2) + bsub;

    const int s = off[g];
    const int e = off[g + 1];

    const uint2* in2 = (const uint2*)in + ((size_t)b << 18) + lane;

    float4 acc = make_float4(0.f, 0.f, 0.f, 0.f);
    for (int cs = s; cs < e; cs += 256) {
        int cnt = e - cs;
        if (cnt > 256) cnt = 256;
        __syncthreads();
        if (threadIdx.x < cnt) sidx[threadIdx.x] = adj[cs + threadIdx.x];
        __syncthreads();
        for (int i = 0; i < cnt; i++) {
            uint2 v = in2[(size_t)sidx[i] * 64];
            float2 f0 = __half22float2(*reinterpret_cast<__half2*>(&v.x));
            float2 f1 = __half22float2(*reinterpret_cast<__half2*>(&v.y));
            acc.x += f0.x; acc.y += f0.y; acc.z += f1.x; acc.w += f1.y;
        }
    }

    const float sc = inv[g];
    acc.x *= sc; acc.y *= sc; acc.z *= sc; acc.w *= sc;

    if (out_sel == 3) {
        // cols c = 4*lane + i ; within 32-chunk permute c -> (c%4)*8 + (c/4)%8
        int chunk = lane >> 3;
        int r8 = lane & 7;
        size_t base = ((size_t)b << 20) + ((size_t)g << 8) + (chunk << 5) + r8;
        uint32_t u0, u1, u2, u3;
        asm("cvt.rna.tf32.f32 %0, %1;" : "=r"(u0) : "f"(acc.x));
        asm("cvt.rna.tf32.f32 %0, %1;" : "=r"(u1) : "f"(acc.y));
        asm("cvt.rna.tf32.f32 %0, %1;" : "=r"(u2) : "f"(acc.z));
        asm("cvt.rna.tf32.f32 %0, %1;" : "=r"(u3) : "f"(acc.w));
        g_y[base + 0]  = __uint_as_float(u0);
        g_y[base + 8]  = __uint_as_float(u1);
        g_y[base + 16] = __uint_as_float(u2);
        g_y[base + 24] = __uint_as_float(u3);
    } else {
        __half* outp = (out_sel == 1) ? g_ahf : g_ehf;
        __half2 q0 = __floats2half2_rn(acc.x, acc.y);
        __half2 q1 = __floats2half2_rn(acc.z, acc.w);
        uint2 o;
        o.x = *(uint32_t*)&q0;
        o.y = *(uint32_t*)&q1;
        ((uint2*)outp)[((size_t)b << 18) + (size_t)g * 64 + lane] = o;
    }
}

// ---------------- tensor-core GEMM: out = g_y(perm,tf32) @ W12p + u*bvec + b2 ----
// BM=128, BN=128, k-chunk 32, 256 threads (8 warps: 4 m x 2 n), warp tile 32x64.
#define GPAD 36

__device__ __forceinline__ void mma_tf32(float4& c,
                                         uint32_t a0, uint32_t a1, uint32_t a2, uint32_t a3,
                                         uint32_t b0, uint32_t b1) {
    asm("mma.sync.aligned.m16n8k8.row.col.f32.tf32.tf32.f32 "
        "{%0,%1,%2,%3}, {%4,%5,%6,%7}, {%8,%9}, {%0,%1,%2,%3};"
        : "+f"(c.x), "+f"(c.y), "+f"(c.z), "+f"(c.w)
        : "r"(a0), "r"(a1), "r"(a2), "r"(a3), "r"(b0), "r"(b1));
}

__global__ __launch_bounds__(256, 1) void gemm_tc(float* __restrict__ C,
                                                  const float* __restrict__ b2) {
    __shared__ float As[128 * GPAD];
    __shared__ float Bs[128 * GPAD];

    const int tid  = threadIdx.x;
    const int wid  = tid >> 5;
    const int lane = tid & 31;
    const int g    = lane >> 2;
    const int t    = lane & 3;
    const int wm   = wid & 3;      // 4 warps along M (32 rows each)
    const int wn   = wid >> 2;     // 2 warps along N (64 cols each)
    const int m0   = blockIdx.x * 128;
    const int n0   = blockIdx.y * 128;

    float4 acc[2][8];
#pragma unroll
    for (int mt = 0; mt < 2; mt++)
#pragma unroll
        for (int nt = 0; nt < 8; nt++) acc[mt][nt] = make_float4(0.f, 0.f, 0.f, 0.f);

    // device symbols referenced from device code (host cannot pass them!)
    const float4* A4 = (const float4*)g_y;
    const float4* B4 = (const float4*)g_W12p;

    // ldg assignment: f4 id = i*256 + tid ; row = id>>3, c4 = id&7
    float4 ra[4], rb[4];
#pragma unroll
    for (int i = 0; i < 4; i++) {
        int id = i * 256 + tid;
        int row = id >> 3, c4 = id & 7;
        ra[i] = A4[((size_t)(m0 + row) << 6) + c4];
        rb[i] = B4[((size_t)(n0 + row) << 6) + c4];
    }

    for (int kc = 0; kc < 8; kc++) {
#pragma unroll
        for (int i = 0; i < 4; i++) {
            int id = i * 256 + tid;
            int row = id >> 3, c4 = id & 7;
            *(float4*)&As[row * GPAD + c4 * 4] = ra[i];
            *(float4*)&Bs[row * GPAD + c4 * 4] = rb[i];
        }
        __syncthreads();
        if (kc < 7) {
#pragma unroll
            for (int i = 0; i < 4; i++) {
                int id = i * 256 + tid;
                int row = id >> 3, c4 = id & 7;
                ra[i] = A4[((size_t)(m0 + row) << 6) + (kc + 1) * 8 + c4];
                rb[i] = B4[((size_t)(n0 + row) << 6) + (kc + 1) * 8 + c4];
            }
        }
#pragma unroll
        for (int half = 0; half < 2; half++) {
            float4 alo[2], ahi[2], bb[8];
#pragma unroll
            for (int mt = 0; mt < 2; mt++) {
                int r = wm * 32 + mt * 16 + g;
                alo[mt] = *(const float4*)&As[r * GPAD + t * 8 + half * 4];
                ahi[mt] = *(const float4*)&As[(r + 8) * GPAD + t * 8 + half * 4];
            }
#pragma unroll
            for (int nt = 0; nt < 8; nt++) {
                int n = wn * 64 + nt * 8 + g;
                bb[nt] = *(const float4*)&Bs[n * GPAD + t * 8 + half * 4];
            }
#pragma unroll
            for (int mt = 0; mt < 2; mt++) {
                uint32_t a0j0 = __float_as_uint(alo[mt].x), a2j0 = __float_as_uint(alo[mt].y);
                uint32_t a0j1 = __float_as_uint(alo[mt].z), a2j1 = __float_as_uint(alo[mt].w);
                uint32_t a1j0 = __float_as_uint(ahi[mt].x), a3j0 = __float_as_uint(ahi[mt].y);
                uint32_t a1j1 = __float_as_uint(ahi[mt].z), a3j1 = __float_as_uint(ahi[mt].w);
#pragma unroll
                for (int nt = 0; nt < 8; nt++) {
                    mma_tf32(acc[mt][nt], a0j0, a1j0, a2j0, a3j0,
                             __float_as_uint(bb[nt].x), __float_as_uint(bb[nt].y));
                    mma_tf32(acc[mt][nt], a0j1, a1j1, a2j1, a3j1,
                             __float_as_uint(bb[nt].z), __float_as_uint(bb[nt].w));
                }
            }
        }
        __syncthreads();
    }

    // epilogue: c += u(row)*bvec[col] + b2[col]
#pragma unroll
    for (int mt = 0; mt < 2; mt++) {
        int r = m0 + wm * 32 + mt * 16 + g;
        float u0 = (g_dinv[r & (NN - 1)] > 0.f) ? 1.f : 0.f;
        float u1 = (g_dinv[(r + 8) & (NN - 1)] > 0.f) ? 1.f : 0.f;
#pragma unroll
        for (int nt = 0; nt < 8; nt++) {
            int col = n0 + wn * 64 + nt * 8 + 2 * t;
            float bv0 = g_bvec[col], bv1 = g_bvec[col + 1];
            float c0 = b2[col], c1 = b2[col + 1];
            float2 lo = make_float2(acc[mt][nt].x + u0 * bv0 + c0,
                                    acc[mt][nt].y + u0 * bv1 + c1);
            float2 hi = make_float2(acc[mt][nt].z + u1 * bv0 + c0,
                                    acc[mt][nt].w + u1 * bv1 + c1);
            *(float2*)&C[(size_t)r * CC + col] = lo;
            *(float2*)&C[(size_t)(r + 8) * CC + col] = hi;
        }
    }
}

// ---------------- launch ----------------
extern "C" void kernel_launch(void* const* d_in, const int* in_sizes, int n_in,
                              void* d_out, int out_size) {
    const float* x    = (const float*)d_in[0];
    const int*   hidx = (const int*)d_in[1];   // [2, NNZ]: row0 src, row1 dst
    const float* W1   = (const float*)d_in[2];
    const float* b1   = (const float*)d_in[3];
    const float* W2   = (const float*)d_in[4];
    const float* b2   = (const float*)d_in[5];
    float* out = (float*)d_out;

    // setup: degrees, CSRs, fused weights, X -> fp16
    zero_kernel<<<16, 256>>>();
    deg_kernel<<<NNZ / 256, 256>>>(hidx);
    scan_kernel<<<2, 1024>>>();
    fill_kernel<<<NNZ / 256, 256>>>(hidx);
    w12_kernel<<<CC + 1, 256>>>(W1, b1, W2);
    conv_kernel<<<(BB * NN * CC) / (256 * 8), 256>>>(x);

    // S application #1: X_h(g_ahf) -> g_ehf -> Z1(g_ahf)  [16-batch L2 groups]
    for (int bb = 0; bb < BB; bb += 16) {
        agg_hf<<<dim3(EE, 4), 256>>>(1, 2, 1, bb);
        agg_hf<<<dim3(NN, 4), 256>>>(2, 1, 0, bb);
    }
    // S application #2: Z1(g_ahf) -> g_ehf -> g_y (fp32, tf32 k-permuted)
    for (int bb = 0; bb < BB; bb += 16) {
        agg_hf<<<dim3(EE, 4), 256>>>(1, 2, 1, bb);
        agg_hf<<<dim3(NN, 4), 256>>>(2, 3, 0, bb);
    }

    // out = Z2 @ W12 + u*bvec + b2
    gemm_tc<<<dim3((BB * NN) / 128, CC / 128), 256>>>(out, b2);
}

// round 10
// speedup vs baseline: 1.5848x; 1.0989x over previous
#include <cuda_runtime.h>
#include <cuda_fp16.h>
#include <cstdint>

// Problem constants
#define BB   64
#define NN   4096
#define EE   4096
#define NNZ  32768
#define CC   256

// ---------------- static device scratch (no allocs allowed) ----------------
__device__ float g_y   [(size_t)BB * NN * CC];     // 268 MB (GEMM A, tf32 perm)
__device__ __half g_ahf[(size_t)BB * NN * CC];     // 134 MB (X_h, then Z1)
__device__ __half g_ehf[(size_t)BB * EE * CC];     // 134 MB (edge intermediate)
__device__ float g_W12p[CC * CC];                  // W1@W2, n-major, k-perm, tf32
__device__ float g_bvec[CC];                       // b1@W2

__device__ int   g_deg_e[EE], g_deg_n[NN];
__device__ int   g_off_e[EE + 1], g_off_n[NN + 1];
__device__ int   g_cur_e[EE], g_cur_n[NN];
__device__ int   g_adj_e[NNZ];   // grouped by dst(edge), values = src(node)
__device__ int   g_adj_n[NNZ];   // grouped by src(node), values = dst(edge)
__device__ float g_binv[EE], g_dinv[NN];

// ---------------- setup kernels ----------------
__global__ void zero_kernel() {
    int i = blockIdx.x * blockDim.x + threadIdx.x;
    if (i < EE) g_deg_e[i] = 0;
    if (i < NN) g_deg_n[i] = 0;
}

__global__ void deg_kernel(const int* __restrict__ hidx) {
    int i = blockIdx.x * blockDim.x + threadIdx.x;
    if (i >= NNZ) return;
    int s = hidx[i];
    int d = hidx[NNZ + i];
    atomicAdd(&g_deg_n[s], 1);
    atomicAdd(&g_deg_e[d], 1);
}

__global__ void scan_kernel() {
    const int which = blockIdx.x;
    const int* deg = which ? g_deg_n : g_deg_e;
    int* off       = which ? g_off_n : g_off_e;
    int* cur       = which ? g_cur_n : g_cur_e;
    float* inv     = which ? g_dinv  : g_binv;

    __shared__ int sm[1024];
    int t = threadIdx.x;
    int d0 = deg[t * 4 + 0];
    int d1 = deg[t * 4 + 1];
    int d2 = deg[t * 4 + 2];
    int d3 = deg[t * 4 + 3];
    int s = d0 + d1 + d2 + d3;
    sm[t] = s;
    __syncthreads();
    for (int o = 1; o < 1024; o <<= 1) {
        int v = (t >= o) ? sm[t - o] : 0;
        __syncthreads();
        sm[t] += v;
        __syncthreads();
    }
    int base = sm[t] - s;
    int p0 = base;
    int p1 = p0 + d0;
    int p2 = p1 + d1;
    int p3 = p2 + d2;
    off[t * 4 + 0] = p0; cur[t * 4 + 0] = p0;
    off[t * 4 + 1] = p1; cur[t * 4 + 1] = p1;
    off[t * 4 + 2] = p2; cur[t * 4 + 2] = p2;
    off[t * 4 + 3] = p3; cur[t * 4 + 3] = p3;
    inv[t * 4 + 0] = d0 > 0 ? 1.0f / (float)d0 : 0.0f;
    inv[t * 4 + 1] = d1 > 0 ? 1.0f / (float)d1 : 0.0f;
    inv[t * 4 + 2] = d2 > 0 ? 1.0f / (float)d2 : 0.0f;
    inv[t * 4 + 3] = d3 > 0 ? 1.0f / (float)d3 : 0.0f;
    if (t == 1023) off[4096] = p3 + d3;
}

__global__ void fill_kernel(const int* __restrict__ hidx) {
    int i = blockIdx.x * blockDim.x + threadIdx.x;
    if (i >= NNZ) return;
    int s = hidx[i];
    int d = hidx[NNZ + i];
    int p = atomicAdd(&g_cur_e[d], 1);
    g_adj_e[p] = s;
    int q = atomicAdd(&g_cur_n[s], 1);
    g_adj_n[q] = d;
}

// X fp32 -> g_ahf fp16 (8 elements per thread)
__global__ __launch_bounds__(256) void conv_kernel(const float* __restrict__ x) {
    size_t id = (size_t)blockIdx.x * 256 + threadIdx.x;
    const float4* x4 = (const float4*)x;
    float4 a = x4[id * 2 + 0];
    float4 b = x4[id * 2 + 1];
    __half2 p0 = __floats2half2_rn(a.x, a.y);
    __half2 p1 = __floats2half2_rn(a.z, a.w);
    __half2 p2 = __floats2half2_rn(b.x, b.y);
    __half2 p3 = __floats2half2_rn(b.z, b.w);
    uint4 o;
    o.x = *(uint32_t*)&p0; o.y = *(uint32_t*)&p1;
    o.z = *(uint32_t*)&p2; o.w = *(uint32_t*)&p3;
    ((uint4*)g_ahf)[id] = o;
}

// W12 = W1 @ W2 (stored n-major, k-permuted, tf32) ; bvec = b1 @ W2.
__global__ void w12_kernel(const float* __restrict__ W1,
                           const float* __restrict__ b1,
                           const float* __restrict__ W2) {
    __shared__ float row[CC];
    int j = threadIdx.x;
    int i = blockIdx.x;
    if (i < CC) {
        row[j] = W1[i * CC + j];
        __syncthreads();
        float acc = 0.0f;
#pragma unroll 8
        for (int k = 0; k < CC; k++) acc += row[k] * W2[k * CC + j];
        // k index = i ; permute within 32-chunk: c -> (c%4)*8 + (c/4)%8, tf32
        int cl = i & 31;
        int s = (i & ~31) + ((cl & 3) << 3) + (cl >> 2);
        uint32_t u;
        asm("cvt.rna.tf32.f32 %0, %1;" : "=r"(u) : "f"(acc));
        g_W12p[j * CC + s] = __uint_as_float(u);
    } else {
        row[j] = b1[j];
        __syncthreads();
        float acc = 0.0f;
#pragma unroll 8
        for (int k = 0; k < CC; k++) acc += row[k] * W2[k * CC + j];
        g_bvec[j] = acc;
    }
}

// ---------------- fp16 aggregation (one S half-step) ----------------
// One block: segment g x 8 batches. 32 lanes x uint4 (8 fp16 ch) cover C=256.
// Batch slab = 4096 rows * 32 uint4 = 2^17 uint4.
// in_sel: 1 = g_ahf, 2 = g_ehf
// out_sel: 1 = g_ahf (fp16), 2 = g_ehf (fp16), 3 = g_y (fp32, tf32 k-permuted)
__device__ __forceinline__ void add8(float* a, uint4 v) {
    float2 f0 = __half22float2(*reinterpret_cast<__half2*>(&v.x));
    float2 f1 = __half22float2(*reinterpret_cast<__half2*>(&v.y));
    float2 f2 = __half22float2(*reinterpret_cast<__half2*>(&v.z));
    float2 f3 = __half22float2(*reinterpret_cast<__half2*>(&v.w));
    a[0] += f0.x; a[1] += f0.y; a[2] += f1.x; a[3] += f1.y;
    a[4] += f2.x; a[5] += f2.y; a[6] += f3.x; a[7] += f3.y;
}

__global__ __launch_bounds__(256) void agg_hf(int in_sel, int out_sel,
                                              int use_edge_csr) {
    const int* off   = use_edge_csr ? g_off_e : g_off_n;
    const int* adj   = use_edge_csr ? g_adj_e : g_adj_n;
    const float* inv = use_edge_csr ? g_binv  : g_dinv;
    const __half* in = (in_sel == 1) ? g_ahf : g_ehf;

    const int g    = blockIdx.x;
    const int lane = threadIdx.x & 31;
    const int bsub = threadIdx.x >> 5;
    const int b    = (blockIdx.y << 3) + bsub;

    const int s = off[g];
    const int e = off[g + 1];

    const uint4* in4 = (const uint4*)in + ((size_t)b << 17) + lane;

    float a0[8], a1[8];
#pragma unroll
    for (int i = 0; i < 8; i++) { a0[i] = 0.f; a1[i] = 0.f; }

    int j = s;
    for (; j + 4 <= e; j += 4) {
        uint4 v0 = in4[(size_t)adj[j + 0] * 32];
        uint4 v1 = in4[(size_t)adj[j + 1] * 32];
        uint4 v2 = in4[(size_t)adj[j + 2] * 32];
        uint4 v3 = in4[(size_t)adj[j + 3] * 32];
        add8(a0, v0); add8(a1, v1); add8(a0, v2); add8(a1, v3);
    }
    for (; j < e; j++) {
        uint4 v = in4[(size_t)adj[j] * 32];
        add8(a0, v);
    }

    const float sc = inv[g];
#pragma unroll
    for (int i = 0; i < 8; i++) a0[i] = (a0[i] + a1[i]) * sc;

    if (out_sel == 3) {
        // channel c = 8*lane + i ; tf32 perm within 32-chunk: p = (c%4)*8 + (c/4)%8
        // pairs (i, i+4) -> adjacent positions: float2 stores at +0,+8,+16,+24
        uint32_t u[8];
#pragma unroll
        for (int i = 0; i < 8; i++)
            asm("cvt.rna.tf32.f32 %0, %1;" : "=r"(u[i]) : "f"(a0[i]));
        size_t base = ((size_t)b << 20) + ((size_t)g << 8)
                    + ((size_t)(lane >> 2) << 5) + 2 * (lane & 3);
#pragma unroll
        for (int i = 0; i < 4; i++) {
            float2 o = make_float2(__uint_as_float(u[i]), __uint_as_float(u[i + 4]));
            *(float2*)&g_y[base + i * 8] = o;
        }
    } else {
        __half* outp = (out_sel == 1) ? g_ahf : g_ehf;
        __half2 q0 = __floats2half2_rn(a0[0], a0[1]);
        __half2 q1 = __floats2half2_rn(a0[2], a0[3]);
        __half2 q2 = __floats2half2_rn(a0[4], a0[5]);
        __half2 q3 = __floats2half2_rn(a0[6], a0[7]);
        uint4 o;
        o.x = *(uint32_t*)&q0; o.y = *(uint32_t*)&q1;
        o.z = *(uint32_t*)&q2; o.w = *(uint32_t*)&q3;
        ((uint4*)outp)[((size_t)b << 17) + (size_t)g * 32 + lane] = o;
    }
}

// ---------------- tensor-core GEMM: out = g_y(perm,tf32) @ W12p + u*bvec + b2 ----
// BM=128, BN=128, k-chunk 32, 256 threads (8 warps: 4 m x 2 n), warp tile 32x64.
#define GPAD 36

__device__ __forceinline__ void mma_tf32(float4& c,
                                         uint32_t a0, uint32_t a1, uint32_t a2, uint32_t a3,
                                         uint32_t b0, uint32_t b1) {
    asm("mma.sync.aligned.m16n8k8.row.col.f32.tf32.tf32.f32 "
        "{%0,%1,%2,%3}, {%4,%5,%6,%7}, {%8,%9}, {%0,%1,%2,%3};"
        : "+f"(c.x), "+f"(c.y), "+f"(c.z), "+f"(c.w)
        : "r"(a0), "r"(a1), "r"(a2), "r"(a3), "r"(b0), "r"(b1));
}

__global__ __launch_bounds__(256, 1) void gemm_tc(float* __restrict__ C,
                                                  const float* __restrict__ b2) {
    __shared__ float As[128 * GPAD];
    __shared__ float Bs[128 * GPAD];

    const int tid  = threadIdx.x;
    const int wid  = tid >> 5;
    const int lane = tid & 31;
    const int g    = lane >> 2;
    const int t    = lane & 3;
    const int wm   = wid & 3;      // 4 warps along M (32 rows each)
    const int wn   = wid >> 2;     // 2 warps along N (64 cols each)
    const int m0   = blockIdx.x * 128;
    const int n0   = blockIdx.y * 128;

    float4 acc[2][8];
#pragma unroll
    for (int mt = 0; mt < 2; mt++)
#pragma unroll
        for (int nt = 0; nt < 8; nt++) acc[mt][nt] = make_float4(0.f, 0.f, 0.f, 0.f);

    // device symbols referenced from device code (host cannot pass them!)
    const float4* A4 = (const float4*)g_y;
    const float4* B4 = (const float4*)g_W12p;

    // ldg assignment: f4 id = i*256 + tid ; row = id>>3, c4 = id&7
    float4 ra[4], rb[4];
#pragma unroll
    for (int i = 0; i < 4; i++) {
        int id = i * 256 + tid;
        int row = id >> 3, c4 = id & 7;
        ra[i] = A4[((size_t)(m0 + row) << 6) + c4];
        rb[i] = B4[((size_t)(n0 + row) << 6) + c4];
    }

    for (int kc = 0; kc < 8; kc++) {
#pragma unroll
        for (int i = 0; i < 4; i++) {
            int id = i * 256 + tid;
            int row = id >> 3, c4 = id & 7;
            *(float4*)&As[row * GPAD + c4 * 4] = ra[i];
            *(float4*)&Bs[row * GPAD + c4 * 4] = rb[i];
        }
        __syncthreads();
        if (kc < 7) {
#pragma unroll
            for (int i = 0; i < 4; i++) {
                int id = i * 256 + tid;
                int row = id >> 3, c4 = id & 7;
                ra[i] = A4[((size_t)(m0 + row) << 6) + (kc + 1) * 8 + c4];
                rb[i] = B4[((size_t)(n0 + row) << 6) + (kc + 1) * 8 + c4];
            }
        }
#pragma unroll
        for (int half = 0; half < 2; half++) {
            float4 alo[2], ahi[2], bb[8];
#pragma unroll
            for (int mt = 0; mt < 2; mt++) {
                int r = wm * 32 + mt * 16 + g;
                alo[mt] = *(const float4*)&As[r * GPAD + t * 8 + half * 4];
                ahi[mt] = *(const float4*)&As[(r + 8) * GPAD + t * 8 + half * 4];
            }
#pragma unroll
            for (int nt = 0; nt < 8; nt++) {
                int n = wn * 64 + nt * 8 + g;
                bb[nt] = *(const float4*)&Bs[n * GPAD + t * 8 + half * 4];
            }
#pragma unroll
            for (int mt = 0; mt < 2; mt++) {
                uint32_t a0j0 = __float_as_uint(alo[mt].x), a2j0 = __float_as_uint(alo[mt].y);
                uint32_t a0j1 = __float_as_uint(alo[mt].z), a2j1 = __float_as_uint(alo[mt].w);
                uint32_t a1j0 = __float_as_uint(ahi[mt].x), a3j0 = __float_as_uint(ahi[mt].y);
                uint32_t a1j1 = __float_as_uint(ahi[mt].z), a3j1 = __float_as_uint(ahi[mt].w);
#pragma unroll
                for (int nt = 0; nt < 8; nt++) {
                    mma_tf32(acc[mt][nt], a0j0, a1j0, a2j0, a3j0,
                             __float_as_uint(bb[nt].x), __float_as_uint(bb[nt].y));
                    mma_tf32(acc[mt][nt], a0j1, a1j1, a2j1, a3j1,
                             __float_as_uint(bb[nt].z), __float_as_uint(bb[nt].w));
                }
            }
        }
        __syncthreads();
    }

    // epilogue: c += u(row)*bvec[col] + b2[col]
#pragma unroll
    for (int mt = 0; mt < 2; mt++) {
        int r = m0 + wm * 32 + mt * 16 + g;
        float u0 = (g_dinv[r & (NN - 1)] > 0.f) ? 1.f : 0.f;
        float u1 = (g_dinv[(r + 8) & (NN - 1)] > 0.f) ? 1.f : 0.f;
#pragma unroll
        for (int nt = 0; nt < 8; nt++) {
            int col = n0 + wn * 64 + nt * 8 + 2 * t;
            float bv0 = g_bvec[col], bv1 = g_bvec[col + 1];
            float c0 = b2[col], c1 = b2[col + 1];
            float2 lo = make_float2(acc[mt][nt].x + u0 * bv0 + c0,
                                    acc[mt][nt].y + u0 * bv1 + c1);
            float2 hi = make_float2(acc[mt][nt].z + u1 * bv0 + c0,
                                    acc[mt][nt].w + u1 * bv1 + c1);
            *(float2*)&C[(size_t)r * CC + col] = lo;
            *(float2*)&C[(size_t)(r + 8) * CC + col] = hi;
        }
    }
}

// ---------------- launch ----------------
extern "C" void kernel_launch(void* const* d_in, const int* in_sizes, int n_in,
                              void* d_out, int out_size) {
    const float* x    = (const float*)d_in[0];
    const int*   hidx = (const int*)d_in[1];   // [2, NNZ]: row0 src, row1 dst
    const float* W1   = (const float*)d_in[2];
    const float* b1   = (const float*)d_in[3];
    const float* W2   = (const float*)d_in[4];
    const float* b2   = (const float*)d_in[5];
    float* out = (float*)d_out;

    // setup: degrees, CSRs, fused weights, X -> fp16
    zero_kernel<<<16, 256>>>();
    deg_kernel<<<NNZ / 256, 256>>>(hidx);
    scan_kernel<<<2, 1024>>>();
    fill_kernel<<<NNZ / 256, 256>>>(hidx);
    w12_kernel<<<CC + 1, 256>>>(W1, b1, W2);
    conv_kernel<<<(BB * NN * CC) / (256 * 8), 256>>>(x);

    // S application #1: X_h(g_ahf) -> g_ehf -> Z1(g_ahf)
    agg_hf<<<dim3(EE, BB / 8), 256>>>(1, 2, 1);
    agg_hf<<<dim3(NN, BB / 8), 256>>>(2, 1, 0);
    // S application #2: Z1(g_ahf) -> g_ehf -> g_y (fp32, tf32 k-permuted)
    agg_hf<<<dim3(EE, BB / 8), 256>>>(1, 2, 1);
    agg_hf<<<dim3(NN, BB / 8), 256>>>(2, 3, 0);

    // out = Z2 @ W12 + u*bvec + b2
    gemm_tc<<<dim3((BB * NN) / 128, CC / 128), 256>>>(out, b2);
}

// round 11
// speedup vs baseline: 2.1122x; 1.3328x over previous
#include <cuda_runtime.h>
#include <cuda_fp16.h>
#include <cstdint>

// Problem constants
#define BB   64
#define NN   4096
#define EE   4096
#define NNZ  32768
#define CC   256

// ---------------- static device scratch (no allocs allowed) ----------------
__device__ __half g_ahf[(size_t)BB * NN * CC];     // 134 MB (X_h / Z1 / Z2)
__device__ __half g_ehf[(size_t)BB * EE * CC];     // 134 MB (edge intermediate)
__device__ __half g_W12h[CC * CC];                 // W1@W2, n-major, fp16
__device__ float  g_bvec[CC];                      // b1@W2

__device__ int   g_deg_e[EE], g_deg_n[NN];
__device__ int   g_off_e[EE + 1], g_off_n[NN + 1];
__device__ int   g_cur_e[EE], g_cur_n[NN];
__device__ int   g_adj_e[NNZ];   // grouped by dst(edge), values = src(node)
__device__ int   g_adj_n[NNZ];   // grouped by src(node), values = dst(edge)
__device__ float g_binv[EE], g_dinv[NN];

// ---------------- setup kernels ----------------
__global__ void zero_kernel() {
    int i = blockIdx.x * blockDim.x + threadIdx.x;
    if (i < EE) g_deg_e[i] = 0;
    if (i < NN) g_deg_n[i] = 0;
}

__global__ void deg_kernel(const int* __restrict__ hidx) {
    int i = blockIdx.x * blockDim.x + threadIdx.x;
    if (i >= NNZ) return;
    int s = hidx[i];
    int d = hidx[NNZ + i];
    atomicAdd(&g_deg_n[s], 1);
    atomicAdd(&g_deg_e[d], 1);
}

__global__ void scan_kernel() {
    const int which = blockIdx.x;
    const int* deg = which ? g_deg_n : g_deg_e;
    int* off       = which ? g_off_n : g_off_e;
    int* cur       = which ? g_cur_n : g_cur_e;
    float* inv     = which ? g_dinv  : g_binv;

    __shared__ int sm[1024];
    int t = threadIdx.x;
    int d0 = deg[t * 4 + 0];
    int d1 = deg[t * 4 + 1];
    int d2 = deg[t * 4 + 2];
    int d3 = deg[t * 4 + 3];
    int s = d0 + d1 + d2 + d3;
    sm[t] = s;
    __syncthreads();
    for (int o = 1; o < 1024; o <<= 1) {
        int v = (t >= o) ? sm[t - o] : 0;
        __syncthreads();
        sm[t] += v;
        __syncthreads();
    }
    int base = sm[t] - s;
    int p0 = base;
    int p1 = p0 + d0;
    int p2 = p1 + d1;
    int p3 = p2 + d2;
    off[t * 4 + 0] = p0; cur[t * 4 + 0] = p0;
    off[t * 4 + 1] = p1; cur[t * 4 + 1] = p1;
    off[t * 4 + 2] = p2; cur[t * 4 + 2] = p2;
    off[t * 4 + 3] = p3; cur[t * 4 + 3] = p3;
    inv[t * 4 + 0] = d0 > 0 ? 1.0f / (float)d0 : 0.0f;
    inv[t * 4 + 1] = d1 > 0 ? 1.0f / (float)d1 : 0.0f;
    inv[t * 4 + 2] = d2 > 0 ? 1.0f / (float)d2 : 0.0f;
    inv[t * 4 + 3] = d3 > 0 ? 1.0f / (float)d3 : 0.0f;
    if (t == 1023) off[4096] = p3 + d3;
}

__global__ void fill_kernel(const int* __restrict__ hidx) {
    int i = blockIdx.x * blockDim.x + threadIdx.x;
    if (i >= NNZ) return;
    int s = hidx[i];
    int d = hidx[NNZ + i];
    int p = atomicAdd(&g_cur_e[d], 1);
    g_adj_e[p] = s;
    int q = atomicAdd(&g_cur_n[s], 1);
    g_adj_n[q] = d;
}

// X fp32 -> g_ahf fp16 (8 elements per thread)
__global__ __launch_bounds__(256) void conv_kernel(const float* __restrict__ x) {
    size_t id = (size_t)blockIdx.x * 256 + threadIdx.x;
    const float4* x4 = (const float4*)x;
    float4 a = x4[id * 2 + 0];
    float4 b = x4[id * 2 + 1];
    __half2 p0 = __floats2half2_rn(a.x, a.y);
    __half2 p1 = __floats2half2_rn(a.z, a.w);
    __half2 p2 = __floats2half2_rn(b.x, b.y);
    __half2 p3 = __floats2half2_rn(b.z, b.w);
    uint4 o;
    o.x = *(uint32_t*)&p0; o.y = *(uint32_t*)&p1;
    o.z = *(uint32_t*)&p2; o.w = *(uint32_t*)&p3;
    ((uint4*)g_ahf)[id] = o;
}

// W12 = W1 @ W2 (stored n-major fp16) ; bvec = b1 @ W2.
__global__ void w12_kernel(const float* __restrict__ W1,
                           const float* __restrict__ b1,
                           const float* __restrict__ W2) {
    __shared__ float row[CC];
    int j = threadIdx.x;
    int i = blockIdx.x;
    if (i < CC) {
        row[j] = W1[i * CC + j];
        __syncthreads();
        float acc = 0.0f;
#pragma unroll 8
        for (int k = 0; k < CC; k++) acc += row[k] * W2[k * CC + j];
        // n-major: [n=j][k=i]
        g_W12h[j * CC + i] = __float2half_rn(acc);
    } else {
        row[j] = b1[j];
        __syncthreads();
        float acc = 0.0f;
#pragma unroll 8
        for (int k = 0; k < CC; k++) acc += row[k] * W2[k * CC + j];
        g_bvec[j] = acc;
    }
}

// ---------------- fp16 aggregation (one S half-step) ----------------
// One block: segment g x 8 batches. 32 lanes x uint4 (8 fp16 ch) cover C=256.
// Batch slab = 4096 rows * 32 uint4 = 2^17 uint4.
// in_sel: 1 = g_ahf, 2 = g_ehf ; out_sel: 1 = g_ahf, 2 = g_ehf
__device__ __forceinline__ void add8(float* a, uint4 v) {
    float2 f0 = __half22float2(*reinterpret_cast<__half2*>(&v.x));
    float2 f1 = __half22float2(*reinterpret_cast<__half2*>(&v.y));
    float2 f2 = __half22float2(*reinterpret_cast<__half2*>(&v.z));
    float2 f3 = __half22float2(*reinterpret_cast<__half2*>(&v.w));
    a[0] += f0.x; a[1] += f0.y; a[2] += f1.x; a[3] += f1.y;
    a[4] += f2.x; a[5] += f2.y; a[6] += f3.x; a[7] += f3.y;
}

__global__ __launch_bounds__(256) void agg_hf(int in_sel, int out_sel,
                                              int use_edge_csr) {
    const int* off   = use_edge_csr ? g_off_e : g_off_n;
    const int* adj   = use_edge_csr ? g_adj_e : g_adj_n;
    const float* inv = use_edge_csr ? g_binv  : g_dinv;
    const __half* in = (in_sel == 1) ? g_ahf : g_ehf;

    const int g    = blockIdx.x;
    const int lane = threadIdx.x & 31;
    const int bsub = threadIdx.x >> 5;
    const int b    = (blockIdx.y << 3) + bsub;

    const int s = off[g];
    const int e = off[g + 1];

    const uint4* in4 = (const uint4*)in + ((size_t)b << 17) + lane;

    float a0[8], a1[8];
#pragma unroll
    for (int i = 0; i < 8; i++) { a0[i] = 0.f; a1[i] = 0.f; }

    int j = s;
    for (; j + 4 <= e; j += 4) {
        uint4 v0 = in4[(size_t)adj[j + 0] * 32];
        uint4 v1 = in4[(size_t)adj[j + 1] * 32];
        uint4 v2 = in4[(size_t)adj[j + 2] * 32];
        uint4 v3 = in4[(size_t)adj[j + 3] * 32];
        add8(a0, v0); add8(a1, v1); add8(a0, v2); add8(a1, v3);
    }
    for (; j < e; j++) {
        uint4 v = in4[(size_t)adj[j] * 32];
        add8(a0, v);
    }

    const float sc = inv[g];
#pragma unroll
    for (int i = 0; i < 8; i++) a0[i] = (a0[i] + a1[i]) * sc;

    __half* outp = (out_sel == 1) ? g_ahf : g_ehf;
    __half2 q0 = __floats2half2_rn(a0[0], a0[1]);
    __half2 q1 = __floats2half2_rn(a0[2], a0[3]);
    __half2 q2 = __floats2half2_rn(a0[4], a0[5]);
    __half2 q3 = __floats2half2_rn(a0[6], a0[7]);
    uint4 o;
    o.x = *(uint32_t*)&q0; o.y = *(uint32_t*)&q1;
    o.z = *(uint32_t*)&q2; o.w = *(uint32_t*)&q3;
    ((uint4*)outp)[((size_t)b << 17) + (size_t)g * 32 + lane] = o;
}

// ---------------- fp16 tensor-core GEMM: out = Z2 @ W12 + u*bvec + b2 ----
// A = g_ahf [M,256] fp16 row-major; B = g_W12h [n][k] fp16.
// BM=128, BN=128, BK=32, 256 threads (8 warps: 4 m x 2 n), warp tile 32x64.
// mma.m16n8k16, fragments via ldmatrix.x4 on padded smem (40 halfs/row).
#define APAD 40

__device__ __forceinline__ void ldm_x4(uint32_t& r0, uint32_t& r1,
                                       uint32_t& r2, uint32_t& r3, uint32_t addr) {
    asm volatile("ldmatrix.sync.aligned.m8n8.x4.shared.b16 {%0,%1,%2,%3}, [%4];"
                 : "=r"(r0), "=r"(r1), "=r"(r2), "=r"(r3) : "r"(addr));
}

__device__ __forceinline__ void mma_f16(float4& c,
                                        uint32_t a0, uint32_t a1, uint32_t a2, uint32_t a3,
                                        uint32_t b0, uint32_t b1) {
    asm volatile("mma.sync.aligned.m16n8k16.row.col.f32.f16.f16.f32 "
        "{%0,%1,%2,%3}, {%4,%5,%6,%7}, {%8,%9}, {%0,%1,%2,%3};"
        : "+f"(c.x), "+f"(c.y), "+f"(c.z), "+f"(c.w)
        : "r"(a0), "r"(a1), "r"(a2), "r"(a3), "r"(b0), "r"(b1));
}

__global__ __launch_bounds__(256) void gemm_hf(float* __restrict__ C,
                                               const float* __restrict__ b2) {
    __shared__ __align__(16) __half As[128 * APAD];
    __shared__ __align__(16) __half Bs[128 * APAD];

    const int tid  = threadIdx.x;
    const int wid  = tid >> 5;
    const int lane = tid & 31;
    const int g    = lane >> 2;
    const int t    = lane & 3;
    const int wm   = wid & 3;      // 4 warps along M (32 rows each)
    const int wn   = wid >> 2;     // 2 warps along N (64 cols each)
    const int m0   = blockIdx.x * 128;
    const int n0   = blockIdx.y * 128;

    float4 acc[2][8];
#pragma unroll
    for (int mt = 0; mt < 2; mt++)
#pragma unroll
        for (int nt = 0; nt < 8; nt++) acc[mt][nt] = make_float4(0.f, 0.f, 0.f, 0.f);

    const uint4* A4 = (const uint4*)g_ahf;   // 32 uint4 per 256-half row
    const uint4* B4 = (const uint4*)g_W12h;

    // smem ldmatrix lane addresses (precompute as u32 shared addresses)
    const uint32_t sA = (uint32_t)__cvta_generic_to_shared(As);
    const uint32_t sB = (uint32_t)__cvta_generic_to_shared(Bs);
    // A: row add = (lane>>3 & 1)*8, k add = (lane>>4)*8
    const int a_row = (lane & 7) + ((lane >> 3) & 1) * 8;
    const int a_k   = (lane >> 4) * 8;
    // B: n add = (lane>>4)*8, k add = (lane>>3 & 1)*8
    const int b_row = (lane & 7) + (lane >> 4) * 8;
    const int b_k   = ((lane >> 3) & 1) * 8;

    // global ldg assignment: id = i*256+tid ; row = id>>2, c4 = id&3 (4 uint4/row-chunk)
    uint4 ra[2], rb[2];
#pragma unroll
    for (int i = 0; i < 2; i++) {
        int id = i * 256 + tid;
        int row = id >> 2, c4 = id & 3;
        ra[i] = A4[(size_t)(m0 + row) * 32 + c4];
        rb[i] = B4[(size_t)(n0 + row) * 32 + c4];
    }

    for (int kc = 0; kc < 8; kc++) {
#pragma unroll
        for (int i = 0; i < 2; i++) {
            int id = i * 256 + tid;
            int row = id >> 2, c4 = id & 3;
            *(uint4*)&As[row * APAD + c4 * 8] = ra[i];
            *(uint4*)&Bs[row * APAD + c4 * 8] = rb[i];
        }
        __syncthreads();
        if (kc < 7) {
#pragma unroll
            for (int i = 0; i < 2; i++) {
                int id = i * 256 + tid;
                int row = id >> 2, c4 = id & 3;
                ra[i] = A4[(size_t)(m0 + row) * 32 + (kc + 1) * 4 + c4];
                rb[i] = B4[(size_t)(n0 + row) * 32 + (kc + 1) * 4 + c4];
            }
        }
#pragma unroll
        for (int ks = 0; ks < 2; ks++) {
            // A fragments: 2 m-tiles of 16 rows
            uint32_t af[2][4];
#pragma unroll
            for (int mt = 0; mt < 2; mt++) {
                int r = wm * 32 + mt * 16 + a_row;
                uint32_t addr = sA + (uint32_t)(r * APAD + ks * 16 + a_k) * 2;
                ldm_x4(af[mt][0], af[mt][1], af[mt][2], af[mt][3], addr);
            }
            // B fragments: 4 n-pair tiles (16 n rows each) -> 8 n-tiles
            uint32_t bf[8][2];
#pragma unroll
            for (int np = 0; np < 4; np++) {
                int r = wn * 64 + np * 16 + b_row;
                uint32_t addr = sB + (uint32_t)(r * APAD + ks * 16 + b_k) * 2;
                uint32_t r0, r1, r2, r3;
                ldm_x4(r0, r1, r2, r3, addr);
                bf[np * 2 + 0][0] = r0; bf[np * 2 + 0][1] = r1;
                bf[np * 2 + 1][0] = r2; bf[np * 2 + 1][1] = r3;
            }
#pragma unroll
            for (int mt = 0; mt < 2; mt++)
#pragma unroll
                for (int nt = 0; nt < 8; nt++)
                    mma_f16(acc[mt][nt], af[mt][0], af[mt][1], af[mt][2], af[mt][3],
                            bf[nt][0], bf[nt][1]);
        }
        __syncthreads();
    }

    // epilogue: c += u(row)*bvec[col] + b2[col]
#pragma unroll
    for (int mt = 0; mt < 2; mt++) {
        int r = m0 + wm * 32 + mt * 16 + g;
        float u0 = (g_dinv[r & (NN - 1)] > 0.f) ? 1.f : 0.f;
        float u1 = (g_dinv[(r + 8) & (NN - 1)] > 0.f) ? 1.f : 0.f;
#pragma unroll
        for (int nt = 0; nt < 8; nt++) {
            int col = n0 + wn * 64 + nt * 8 + 2 * t;
            float bv0 = g_bvec[col], bv1 = g_bvec[col + 1];
            float c0 = b2[col], c1 = b2[col + 1];
            float2 lo = make_float2(acc[mt][nt].x + u0 * bv0 + c0,
                                    acc[mt][nt].y + u0 * bv1 + c1);
            float2 hi = make_float2(acc[mt][nt].z + u1 * bv0 + c0,
                                    acc[mt][nt].w + u1 * bv1 + c1);
            *(float2*)&C[(size_t)r * CC + col] = lo;
            *(float2*)&C[(size_t)(r + 8) * CC + col] = hi;
        }
    }
}

// ---------------- launch ----------------
extern "C" void kernel_launch(void* const* d_in, const int* in_sizes, int n_in,
                              void* d_out, int out_size) {
    const float* x    = (const float*)d_in[0];
    const int*   hidx = (const int*)d_in[1];   // [2, NNZ]: row0 src, row1 dst
    const float* W1   = (const float*)d_in[2];
    const float* b1   = (const float*)d_in[3];
    const float* W2   = (const float*)d_in[4];
    const float* b2   = (const float*)d_in[5];
    float* out = (float*)d_out;

    // setup: degrees, CSRs, fused weights, X -> fp16
    zero_kernel<<<16, 256>>>();
    deg_kernel<<<NNZ / 256, 256>>>(hidx);
    scan_kernel<<<2, 1024>>>();
    fill_kernel<<<NNZ / 256, 256>>>(hidx);
    w12_kernel<<<CC + 1, 256>>>(W1, b1, W2);
    conv_kernel<<<(BB * NN * CC) / (256 * 8), 256>>>(x);

    // S application #1: X_h(g_ahf) -> g_ehf -> Z1(g_ahf)
    agg_hf<<<dim3(EE, BB / 8), 256>>>(1, 2, 1);
    agg_hf<<<dim3(NN, BB / 8), 256>>>(2, 1, 0);
    // S application #2: Z1(g_ahf) -> g_ehf -> Z2(g_ahf)
    agg_hf<<<dim3(EE, BB / 8), 256>>>(1, 2, 1);
    agg_hf<<<dim3(NN, BB / 8), 256>>>(2, 1, 0);

    // out = Z2 @ W12 + u*bvec + b2   (fp16 mma, fp32 accum)
    gemm_hf<<<dim3((BB * NN) / 128, CC / 128), 256>>>(out, b2);
}